// round 15
// baseline (speedup 1.0000x reference)
#include <cuda_runtime.h>
#include <cstdint>

#define H_ 512
#define W_ 512
#define G_ 83
#define KK 12
#define NB 8
#define NV (G_ * G_)                 // 6889 vertices
#define NF (2 * (G_ - 1) * (G_ - 1)) // 13448 faces
#define HW (H_ * W_)
#define NBNV (NB * NV)               // 55112
#define NTRI (NB * NF)               // 107584 (divisible by 4)

// 16 MB z-buffer scratch, re-initialized each replay by a memset node (0xFF).
__device__ unsigned long long g_zbuf[NB * HW];
// Precomputed projected vertices per (batch, vertex): (x, y, z, 0).
__device__ float4 g_pv[NBNV];
// Faces padded to int4 for single 128-bit loads.
__device__ int4 g_faces4[NF];

// Strict IEEE, non-fused edge function: (a-b)*(c-d) - (e-f)*(g-h)
__device__ __forceinline__ float edgefn(float a, float b, float c, float d,
                                        float e, float f, float g, float h) {
    float t1 = __fmul_rn(__fsub_rn(a, b), __fsub_rn(c, d));
    float t2 = __fmul_rn(__fsub_rn(e, f), __fsub_rn(g, h));
    return __fsub_rn(t1, t2);
}

// Prep: vertex projection + face pad only (fill moved to memset node).
__global__ void prep_kernel(const float* __restrict__ verts,
                            const int* __restrict__ faces) {
    int i = blockIdx.x * blockDim.x + threadIdx.x;
    if (i < NBNV) {
        float vx = verts[3 * i + 0];
        float vy = verts[3 * i + 1];
        float vz = verts[3 * i + 2];
        float r = __fdiv_rn(1.0f, vz);   // bit-identical hoisted projection
        g_pv[i] = make_float4(__fmul_rn(vx, r), __fmul_rn(vy, r), vz, 0.0f);
    }
    if (i < NF) {
        g_faces4[i] = make_int4(faces[3 * i + 0], faces[3 * i + 1],
                                faces[3 * i + 2], 0);
    }
}

// FOUR triangles per warp: 8 lanes each. Per-warp setup instruction count is
// constant regardless of tri/warp, so chip-wide setup cost halves vs 2/warp.
// Each 8-lane group iterates a COMPACT bbox-clipped candidate set (proven
// exact: excluded pixels are >=1px outside the vertex extent where some
// barycentric is <= -1/12 exactly; fp noise cannot flip the w>=0 test).
__global__ void raster_kernel() {
    int gw = (blockIdx.x * blockDim.x + threadIdx.x) >> 5;
    int lane = threadIdx.x & 31;
    if (gw >= NTRI / 4) return;
    int sub = lane & 7;
    int tri = gw * 4 + (lane >> 3);
    int n = tri / NF;
    int f = tri - n * NF;

    int4 fc = g_faces4[f];
    const float4* pv = g_pv + n * NV;
    float4 p0 = pv[fc.x];
    float4 p1 = pv[fc.y];
    float4 p2 = pv[fc.z];
    float x0 = p0.x, y0 = p0.y, z0 = p0.z;
    float x1 = p1.x, y1 = p1.y, z1 = p1.z;
    float x2 = p2.x, y2 = p2.y, z2 = p2.z;

    float area = edgefn(x1, x0, y2, y0, y1, y0, x2, x0);
    bool ok = (z0 > 0.f) && (z1 > 0.f) && (z2 > 0.f) && (fabsf(area) > 1e-9f);
    float invA = __fdiv_rn(1.0f, area);

    float xmn = fminf(x0, fminf(x1, x2));
    float xmx = fmaxf(x0, fmaxf(x1, x2));
    float ymn = fminf(y0, fminf(y1, y2));
    float ymx = fmaxf(y0, fmaxf(y1, y2));
    int fxmn = (int)floorf(xmn);
    int fymn = (int)floorf(ymn);
    int bcx = min(max(fxmn, 0), W_ - KK);
    int bcy = min(max(fymn, 0), H_ - KK);

    int xlo = max(bcx, fxmn);
    int xhi = min(bcx + KK - 1, (int)ceilf(xmx));
    int ylo = max(bcy, fymn);
    int yhi = min(bcy + KK - 1, (int)ceilf(ymx));
    int bw = xhi - xlo + 1;
    int bh = yhi - ylo + 1;
    int cnt = (ok && bw > 0 && bh > 0) ? bw * bh : 0;
    // Exact division t/bw for t < 2^16 via magic multiply.
    unsigned magic = (65536u + (unsigned)bw - 1) / (unsigned)max(bw, 1);

    unsigned long long* zb = g_zbuf + (size_t)n * HW;

    for (int t = sub; t < cnt; t += 8) {
        int oy = (int)(((unsigned)t * magic) >> 16);
        int ox = t - oy * bw;
        int px = xlo + ox;
        int py = ylo + oy;
        float pxf = (float)px, pyf = (float)py;
        float w0 = __fmul_rn(edgefn(x2, x1, pyf, y1, y2, y1, pxf, x1), invA);
        float w1 = __fmul_rn(edgefn(x0, x2, pyf, y2, y0, y2, pxf, x2), invA);
        float w2 = __fsub_rn(__fsub_rn(1.0f, w0), w1);
        if (w0 >= 0.f && w1 >= 0.f && w2 >= 0.f) {
            float depth = __fadd_rn(
                __fadd_rn(__fmul_rn(w0, z0), __fmul_rn(w1, z1)),
                __fmul_rn(w2, z2));
            // Same-pixel ties only arise between DIFFERENT triangles, so
            // packing f preserves the reference's (depth, m) tie-break.
            unsigned long long packed =
                ((unsigned long long)__float_as_uint(depth) << 32) |
                (unsigned int)f;
            atomicMin(zb + py * W_ + px, packed);
        }
    }
}

// Per-pixel shading body: identical arithmetic to the proven version.
__device__ __forceinline__ void shade_pixel(unsigned long long zv, int n,
                                            int pix, const float* vals,
                                            float& ou, float& ov, float& om) {
    float u = 0.f, v = 0.f;
    if (zv != 0xFFFFFFFFFFFFFFFFull) {
        int f = (int)(unsigned int)(zv & 0xFFFFFFFFu);
        int4 fc = g_faces4[f];
        const float4* pv = g_pv + n * NV;
        float4 p0 = pv[fc.x];
        float4 p1 = pv[fc.y];
        float4 p2 = pv[fc.z];
        float x0 = p0.x, y0 = p0.y;
        float x1 = p1.x, y1 = p1.y;
        float x2 = p2.x, y2 = p2.y;
        float area = edgefn(x1, x0, y2, y0, y1, y0, x2, x0);
        float invA = __fdiv_rn(1.0f, area);
        int px = pix & (W_ - 1);
        int py = pix >> 9;
        float pxf = (float)px, pyf = (float)py;
        float w0 = __fmul_rn(edgefn(x2, x1, pyf, y1, y2, y1, pxf, x1), invA);
        float w1 = __fmul_rn(edgefn(x0, x2, pyf, y2, y0, y2, pxf, x2), invA);
        float w2 = __fsub_rn(__fsub_rn(1.0f, w0), w1);
        const float2* vl = reinterpret_cast<const float2*>(vals);
        float2 va = vl[fc.x];
        float2 vbv = vl[fc.y];
        float2 vc = vl[fc.z];
        u = __fadd_rn(
            __fadd_rn(__fmul_rn(w0, va.x), __fmul_rn(w1, vbv.x)),
            __fmul_rn(w2, vc.x));
        v = __fadd_rn(
            __fadd_rn(__fmul_rn(w0, va.y), __fmul_rn(w1, vbv.y)),
            __fmul_rn(w2, vc.y));
    }
    float mask = (u > 0.f || v > 0.f) ? 1.f : 0.f;
    if (mask > 0.f) {
        ou = __fsub_rn(__fmul_rn(2.f, u), 1.f);
        ov = __fsub_rn(__fmul_rn(2.f, v), 1.f);
    } else {
        ou = -10.f;
        ov = -10.f;
    }
    om = mask;
}

// TWO adjacent pixels per thread: one 16B zbuf load, three 8B output stores.
__global__ void shade_kernel(const float* __restrict__ vals,
                             float* __restrict__ out) {
    int gid = blockIdx.x * blockDim.x + threadIdx.x;
    if (gid >= (NB * HW) / 2) return;
    int n = gid / (HW / 2);
    int pix = (gid - n * (HW / 2)) * 2;

    ulonglong2 zv2 = reinterpret_cast<const ulonglong2*>(
        g_zbuf + (size_t)n * HW + pix)[0];

    float ou0, ov0, om0, ou1, ov1, om1;
    shade_pixel(zv2.x, n, pix + 0, vals, ou0, ov0, om0);
    shade_pixel(zv2.y, n, pix + 1, vals, ou1, ov1, om1);

    float2* uplane = reinterpret_cast<float2*>(out + ((size_t)n * 2 + 0) * HW + pix);
    float2* vplane = reinterpret_cast<float2*>(out + ((size_t)n * 2 + 1) * HW + pix);
    float2* mplane = reinterpret_cast<float2*>(out + (size_t)NB * 2 * HW + (size_t)n * HW + pix);
    uplane[0] = make_float2(ou0, ou1);
    vplane[0] = make_float2(ov0, ov1);
    mplane[0] = make_float2(om0, om1);
}

extern "C" void kernel_launch(void* const* d_in, const int* in_sizes, int n_in,
                              void* d_out, int out_size) {
    const float* verts = (const float*)d_in[0];
    const int* faces = (const int*)d_in[1];
    const float* vals = (const float*)d_in[2];
    float* out = (float*)d_out;

    (void)in_sizes; (void)n_in; (void)out_size;

    // Z-buffer sentinel fill as a memset node: all-ones == byte 0xFF.
    void* zbuf_ptr = nullptr;
    cudaGetSymbolAddress(&zbuf_ptr, g_zbuf);
    cudaMemsetAsync(zbuf_ptr, 0xFF, sizeof(unsigned long long) * NB * HW);

    int prepBlocks = (NBNV + 255) / 256;            // covers proj + faces
    prep_kernel<<<prepBlocks, 256>>>(verts, faces);

    int nwarps = NTRI / 4;                 // 26896 warps, 4 tri each
    int rasterBlocks = (nwarps * 32 + 255) / 256;
    raster_kernel<<<rasterBlocks, 256>>>();

    int shadeBlocks = ((NB * HW) / 2 + 255) / 256;
    shade_kernel<<<shadeBlocks, 256>>>(vals, out);
}